// round 6
// baseline (speedup 1.0000x reference)
#include <cuda_runtime.h>

// LocallyConnected1d: out[b,o,l] = sum_{c,k} x[b,c,l+k]*w[o,c,l,k] + bias[o,l]
// B=32, Cin=128, Cout=128, L=2048, K=3, S=1, W=2050, fp32.
//
// f32x2 packed-FMA (b-pairs). 4-buffer cp.async pipeline, prefetch dist 2,
// warp-specialized fills with fully hoisted addressing (zero per-stage
// index math). X layout [ci][w][b(pad 36)] -> compute reads 2x LDS.128,
// conflict-free; fill dst offsets are compile-time constants.

#define CIN     128
#define COUT    128
#define LOUT    2048
#define KW      3
#define WIN     2050

#define L_TILE  32
#define O_TILE  16
#define CC      2                     // Cin per pipeline stage
#define NST     (CIN / CC)            // 64 stages
#define NBUF    4
#define NTHREADS 256

#define XROW    36                    // floats per (ci,w) row: 32 b + 4 pad
#define STAGE_X (CC * 34 * XROW)      // 2448 floats
#define STAGE_W (CC * O_TILE * 96)    // 3072 floats
#define STAGE_F (STAGE_X + STAGE_W)   // 5520 floats = 22080 B
#define SMEM_BYTES (NBUF * STAGE_F * 4)   // 88320 B -> 2 blocks/SM

typedef unsigned long long u64;

static __device__ __forceinline__ u64 pack_dup(float a) {
    u64 r; asm("mov.b64 %0, {%1, %1};" : "=l"(r) : "f"(a)); return r;
}
static __device__ __forceinline__ void unpack2(u64 v, float& a, float& b) {
    asm("mov.b64 {%0, %1}, %2;" : "=f"(a), "=f"(b) : "l"(v));
}
static __device__ __forceinline__ void ffma2(u64& d, u64 a, u64 b) {
    asm("fma.rn.f32x2 %0, %1, %2, %0;" : "+l"(d) : "l"(a), "l"(b));
}
static __device__ __forceinline__ unsigned smem_u32(const void* p) {
    unsigned r;
    asm("{ .reg .u64 t; cvta.to.shared.u64 t, %1; cvt.u32.u64 %0, t; }"
        : "=r"(r) : "l"(p));
    return r;
}
static __device__ __forceinline__ void cpa4(unsigned d, const float* s) {
    asm volatile("cp.async.ca.shared.global [%0], [%1], 4;" :: "r"(d), "l"(s));
}
static __device__ __forceinline__ void cpa16(unsigned d, const float* s) {
    asm volatile("cp.async.cg.shared.global [%0], [%1], 16;" :: "r"(d), "l"(s));
}
#define CP_COMMIT() asm volatile("cp.async.commit_group;" ::: "memory")
#define CP_WAIT1()  asm volatile("cp.async.wait_group 1;" ::: "memory")
#define CP_WAIT0()  asm volatile("cp.async.wait_group 0;" ::: "memory")

__global__ void __launch_bounds__(NTHREADS, 2)
lc1d_kernel(const float* __restrict__ x,
            const float* __restrict__ wgt,
            const float* __restrict__ bias,
            float* __restrict__ out)
{
    extern __shared__ float smem[];
    const unsigned sb = smem_u32(smem);

    const int tid  = threadIdx.x;
    const int lane = tid & 31;            // local l index
    const int warp = tid >> 5;
    const int bp0  = (warp & 3) * 4;      // b-pair group start
    const int og   = (warp >> 2) * 8;     // o group start
    const int l0   = blockIdx.x * L_TILE;
    const int o0   = blockIdx.y * O_TILE;

    // ---- hoisted fill state (warp-specialized; all constant per stage
    //      except one pointer increment) ----
    const bool is_x = (tid < 128);        // warps 0-3: X fill, 4-7: W fill
    const float* src;
    unsigned dst_off;                     // floats within a stage buffer
    long sadv;
    if (is_x) {
        int row = tid >> 1, ci = row >> 5, b = row & 31, w0 = (tid & 1) * 17;
        src     = x + (b * CIN + ci) * WIN + l0 + w0;      // 17 contiguous w
        dst_off = (unsigned)((ci * 34 + w0) * XROW + b);
        sadv    = (long)CC * WIN;
    } else {
        int u = tid - 128, row = u >> 2, ci = row >> 4, oi = row & 15;
        int j0 = (u & 3) * 24;                              // 6 float4 each
        src     = wgt + ((o0 + oi) * CIN + ci) * (LOUT * KW) + l0 * KW + j0;
        dst_off = (unsigned)(STAGE_X + (ci * O_TILE + oi) * 96 + j0);
        sadv    = (long)CC * LOUT * KW;
    }

    auto issue = [&](int buf) {
        unsigned d0 = sb + (unsigned)(buf * STAGE_F + dst_off) * 4u;
        if (is_x) {
            #pragma unroll
            for (int j = 0; j < 17; j++)
                cpa4(d0 + (unsigned)(j * XROW) * 4u, src + j);
        } else {
            #pragma unroll
            for (int c = 0; c < 6; c++)
                cpa16(d0 + (unsigned)c * 16u, src + c * 4);
        }
        src += sadv;
    };

    u64 acc[4][8];
    #pragma unroll
    for (int p = 0; p < 4; p++)
        #pragma unroll
        for (int o = 0; o < 8; o++) acc[p][o] = 0ull;

    // prologue: prefetch stages 0 and 1
    issue(0); CP_COMMIT();
    issue(1); CP_COMMIT();

    #pragma unroll 4
    for (int s = 0; s < NST; s++) {
        if (s + 2 < NST) { CP_WAIT1(); } else { CP_WAIT0(); }
        __syncthreads();                     // stage s visible block-wide

        if (s + 2 < NST) {                   // prefetch s+2 (dist 2)
            issue((s + 2) & (NBUF - 1));
            CP_COMMIT();
        }

        const float* Xb = smem + (s & (NBUF - 1)) * STAGE_F;
        const float* Wb = Xb + STAGE_X;

        #pragma unroll
        for (int ci = 0; ci < CC; ci++) {
            #pragma unroll
            for (int k = 0; k < KW; k++) {
                // x: [ci][w=lane+k][b] rows of 18 u64; bp0 even -> 16B align
                const u64* xp = reinterpret_cast<const u64*>(Xb)
                              + (ci * 34 + lane + k) * (XROW / 2) + bp0;
                ulonglong2 va = *reinterpret_cast<const ulonglong2*>(xp);
                ulonglong2 vb = *reinterpret_cast<const ulonglong2*>(xp + 2);
                // w: stride-3 lane addressing, coprime with 32 banks
                const float* wp = Wb + (ci * O_TILE + og) * 96 + lane * KW + k;
                #pragma unroll
                for (int oi = 0; oi < 8; oi++) {
                    u64 wv = pack_dup(wp[oi * 96]);
                    ffma2(acc[0][oi], va.x, wv);
                    ffma2(acc[1][oi], va.y, wv);
                    ffma2(acc[2][oi], vb.x, wv);
                    ffma2(acc[3][oi], vb.y, wv);
                }
            }
        }
    }

    // epilogue: bias + coalesced stores (l-contiguous)
    const int b0 = (warp & 3) * 8;
    #pragma unroll
    for (int oi = 0; oi < 8; oi++) {
        int o = o0 + og + oi;
        float bv = bias[o * LOUT + l0 + lane];
        #pragma unroll
        for (int p = 0; p < 4; p++) {
            float f0, f1;
            unpack2(acc[p][oi], f0, f1);
            int b = b0 + 2 * p;
            out[(b * COUT + o) * LOUT + l0 + lane]       = f0 + bv;
            out[((b + 1) * COUT + o) * LOUT + l0 + lane] = f1 + bv;
        }
    }
}

extern "C" void kernel_launch(void* const* d_in, const int* in_sizes, int n_in,
                              void* d_out, int out_size)
{
    const float* x    = (const float*)d_in[0];
    const float* wgt  = (const float*)d_in[1];
    const float* bias = (const float*)d_in[2];
    float* out        = (float*)d_out;

    cudaFuncSetAttribute(lc1d_kernel,
                         cudaFuncAttributeMaxDynamicSharedMemorySize, SMEM_BYTES);

    dim3 grid(LOUT / L_TILE, COUT / O_TILE);   // (64, 8) = 512 blocks
    lc1d_kernel<<<grid, NTHREADS, SMEM_BYTES>>>(x, wgt, bias, out);
}

// round 7
// speedup vs baseline: 1.8611x; 1.8611x over previous
#include <cuda_runtime.h>

// LocallyConnected1d: out[b,o,l] = sum_{c,k} x[b,c,l+k]*w[o,c,l,k] + bias[o,l]
// B=32, Cin=128, Cout=128, L=2048, K=3, S=1, W=2050, fp32.
//
// f32x2 packed-FMA (b-pairs, rt2 => 128 FMA/cyc/SM ceiling).
// 4-buffer cp.async pipeline, prefetch distance 2. Warp-structured fills:
// lanes sweep contiguous global addresses (coalesced), per-row offsets are
// compile-time immediates (no per-copy ALU). X layout [ci][bp][w] float2-
// interleaved (R5-proven): compute = 4x LDS.64 conflict-free.

#define CIN     128
#define COUT    128
#define LOUT    2048
#define KW      3
#define WIN     2050

#define L_TILE  32
#define O_TILE  16
#define CC      2                     // Cin per pipeline stage
#define NST     (CIN / CC)            // 64 stages
#define NBUF    4
#define NTHREADS 256

#define XPAD    34                    // u64 (float2) per (ci,bp) row
#define STAGE_X (CC * 16 * XPAD * 2)  // 2176 floats
#define STAGE_W (CC * O_TILE * 96)    // 3072 floats
#define STAGE_F (STAGE_X + STAGE_W)   // 5248 floats
#define STAGE_BYTES (STAGE_F * 4)     // 20992 B
#define SMEM_BYTES (NBUF * STAGE_BYTES)  // 83968 B -> 2 blocks/SM

typedef unsigned long long u64;

static __device__ __forceinline__ u64 pack_dup(float a) {
    u64 r; asm("mov.b64 %0, {%1, %1};" : "=l"(r) : "f"(a)); return r;
}
static __device__ __forceinline__ void unpack2(u64 v, float& a, float& b) {
    asm("mov.b64 {%0, %1}, %2;" : "=f"(a), "=f"(b) : "l"(v));
}
static __device__ __forceinline__ void ffma2(u64& d, u64 a, u64 b) {
    asm("fma.rn.f32x2 %0, %1, %2, %0;" : "+l"(d) : "l"(a), "l"(b));
}
static __device__ __forceinline__ unsigned smem_u32(const void* p) {
    unsigned r;
    asm("{ .reg .u64 t; cvta.to.shared.u64 t, %1; cvt.u32.u64 %0, t; }"
        : "=r"(r) : "l"(p));
    return r;
}
static __device__ __forceinline__ void cpa4(unsigned d, const float* s) {
    asm volatile("cp.async.ca.shared.global [%0], [%1], 4;" :: "r"(d), "l"(s));
}
static __device__ __forceinline__ void cpa16(unsigned d, const float* s) {
    asm volatile("cp.async.cg.shared.global [%0], [%1], 16;" :: "r"(d), "l"(s));
}
#define CP_COMMIT() asm volatile("cp.async.commit_group;" ::: "memory")
#define CP_WAIT1()  asm volatile("cp.async.wait_group 1;" ::: "memory")
#define CP_WAIT0()  asm volatile("cp.async.wait_group 0;" ::: "memory")

__global__ void __launch_bounds__(NTHREADS, 2)
lc1d_kernel(const float* __restrict__ x,
            const float* __restrict__ wgt,
            const float* __restrict__ bias,
            float* __restrict__ out)
{
    extern __shared__ float smem[];
    const unsigned sb = smem_u32(smem);

    const int tid  = threadIdx.x;
    const int lane = tid & 31;            // local l index (compute)
    const int warp = tid >> 5;
    const int bp0  = (warp & 3) * 4;      // b-pair group start (compute)
    const int og   = (warp >> 2) * 8;     // o group start (compute)
    const int l0   = blockIdx.x * L_TILE;
    const int o0   = blockIdx.y * O_TILE;

    // ================= fill state (warp-specialized, hoisted) =============
    // X warps (0-3): 16 rows each; row r = warp*16+i -> ci0=warp>>1, b=b0+i.
    //   main: lanes sweep w=0..31 (coalesced 128B); tail: 16 rows x w=32,33.
    // W warps (4-7): 8 rows each; row r=(warp-4)*8+i -> ci=r>>4, oi=r&15.
    //   lanes 0..23 sweep the 96-float run as float4 (coalesced 384B).
    const bool is_x = (warp < 4);
    const float* srcA;                    // main src (advances CC rows of c)
    const float* srcB = nullptr;          // X tail src
    unsigned dstA, dstB = 0;              // smem float offsets within stage
    long cadv;
    if (is_x) {
        const int ci0 = warp >> 1;
        const int b0f = (warp & 1) * 16;
        srcA = x + ((long)(b0f * CIN + ci0)) * WIN + l0 + lane;
        dstA = (unsigned)((ci0 * 16 + b0f / 2) * 68 + lane * 2);
        srcB = x + ((long)((b0f + (lane >> 1)) * CIN + ci0)) * WIN
                 + l0 + 32 + (lane & 1);
        dstB = (unsigned)(((ci0 * 16 + b0f / 2 + (lane >> 2)) * 34
                           + 32 + (lane & 1)) * 2 + ((lane >> 1) & 1));
        cadv = (long)CC * WIN;
    } else {
        const int ww  = warp - 4;
        const int ci0 = ww >> 1;
        const int oi0 = (ww & 1) * 8;
        srcA = wgt + ((long)((o0 + oi0) * CIN + ci0)) * (LOUT * KW)
                   + l0 * KW + lane * 4;
        dstA = (unsigned)(STAGE_X + (ci0 * 16 + oi0) * 96 + lane * 4);
        cadv = (long)CC * LOUT * KW;
    }

    u64 acc[4][8];
    #pragma unroll
    for (int p = 0; p < 4; p++)
        #pragma unroll
        for (int o = 0; o < 8; o++) acc[p][o] = 0ull;

    // fill for one stage into buffer buf; advances src pointers by CC chans
    #define ISSUE(buf) do {                                                 \
        unsigned d0_ = sb + (unsigned)(buf) * STAGE_BYTES + dstA * 4u;      \
        if (is_x) {                                                         \
            _Pragma("unroll")                                               \
            for (int i_ = 0; i_ < 16; i_++)                                 \
                cpa4(d0_ + (unsigned)(((i_ >> 1) * 68 + (i_ & 1)) * 4),     \
                     srcA + (long)i_ * (CIN * WIN));                        \
            cpa4(sb + (unsigned)(buf) * STAGE_BYTES + dstB * 4u, srcB);     \
            srcB += cadv;                                                   \
        } else if (lane < 24) {                                             \
            _Pragma("unroll")                                               \
            for (int i_ = 0; i_ < 8; i_++)                                  \
                cpa16(d0_ + (unsigned)(i_ * 96 * 4),                        \
                      srcA + (long)i_ * (CIN * LOUT * KW));                 \
        }                                                                   \
        srcA += cadv;                                                       \
    } while (0)

    // prologue: prefetch stages 0,1
    ISSUE(0); CP_COMMIT();
    ISSUE(1); CP_COMMIT();

    #pragma unroll 1
    for (int s = 0; s < NST; s++) {
        if (s + 2 < NST) { CP_WAIT1(); } else { CP_WAIT0(); }
        __syncthreads();                     // stage s visible block-wide

        if (s + 2 < NST) {                   // prefetch s+2 (distance 2)
            const int bnext = (s + 2) & (NBUF - 1);
            ISSUE(bnext);
            CP_COMMIT();
        }

        const float* Xb = smem + (s & (NBUF - 1)) * STAGE_F;
        const float* Wb = Xb + STAGE_X;

        #pragma unroll
        for (int ci = 0; ci < CC; ci++) {
            #pragma unroll
            for (int k = 0; k < KW; k++) {
                const u64* xp = reinterpret_cast<const u64*>(Xb)
                              + (ci * 16 + bp0) * XPAD + lane + k;
                const u64 px0 = xp[0];
                const u64 px1 = xp[XPAD];
                const u64 px2 = xp[2 * XPAD];
                const u64 px3 = xp[3 * XPAD];
                // stride-3 lane addressing: coprime with 32 banks
                const float* wp = Wb + (ci * O_TILE + og) * 96 + lane * KW + k;
                #pragma unroll
                for (int oi = 0; oi < 8; oi++) {
                    u64 wv = pack_dup(wp[oi * 96]);
                    ffma2(acc[0][oi], px0, wv);
                    ffma2(acc[1][oi], px1, wv);
                    ffma2(acc[2][oi], px2, wv);
                    ffma2(acc[3][oi], px3, wv);
                }
            }
        }
    }

    // epilogue: bias + coalesced stores (l-contiguous)
    const int b0 = (warp & 3) * 8;
    #pragma unroll
    for (int oi = 0; oi < 8; oi++) {
        int o = o0 + og + oi;
        float bv = bias[o * LOUT + l0 + lane];
        #pragma unroll
        for (int p = 0; p < 4; p++) {
            float f0, f1;
            unpack2(acc[p][oi], f0, f1);
            int b = b0 + 2 * p;
            out[(b * COUT + o) * LOUT + l0 + lane]       = f0 + bv;
            out[((b + 1) * COUT + o) * LOUT + l0 + lane] = f1 + bv;
        }
    }
}

extern "C" void kernel_launch(void* const* d_in, const int* in_sizes, int n_in,
                              void* d_out, int out_size)
{
    const float* x    = (const float*)d_in[0];
    const float* wgt  = (const float*)d_in[1];
    const float* bias = (const float*)d_in[2];
    float* out        = (float*)d_out;

    cudaFuncSetAttribute(lc1d_kernel,
                         cudaFuncAttributeMaxDynamicSharedMemorySize, SMEM_BYTES);

    dim3 grid(LOUT / L_TILE, COUT / O_TILE);   // (64, 8) = 512 blocks
    lc1d_kernel<<<grid, NTHREADS, SMEM_BYTES>>>(x, wgt, bias, out);
}